// round 5
// baseline (speedup 1.0000x reference)
#include <cuda_runtime.h>
#include <cuda_bf16.h>
#include <cstdint>

#define BATCH 32
#define SEQ   2048
#define EDIM  128
#define HVOC  500000
#define HBASE 257
#define NPOS  (BATCH * SEQ)

#define PPW    8                    // positions per warp
#define DEPTH  3                    // cp.async pipeline stages
#define WPB    8                    // warps per block
#define ROWB   512                  // bytes per gathered row (128 fp32)
#define STAGE_BYTES (6 * ROWB)      // 3072 per position
#define WARP_SMEM   (DEPTH * STAGE_BYTES)   // 9216
#define BLOCK_SMEM  (WPB * WARP_SMEM)       // 73728

#define NWARPS (NPOS / PPW)         // 8192
#define NBLOCKS (NWARPS / WPB)      // 1024

__device__ __forceinline__ uint32_t smem_u32(const void* p) {
    return (uint32_t)__cvta_generic_to_shared(p);
}

__device__ __forceinline__ void cp16(uint32_t dst, const void* src) {
    asm volatile("cp.async.cg.shared.global [%0], [%1], 16;\n"
                 :: "r"(dst), "l"(src) : "memory");
}
__device__ __forceinline__ void cp_commit() {
    asm volatile("cp.async.commit_group;\n" ::: "memory");
}
template <int N>
__device__ __forceinline__ void cp_wait() {
    asm volatile("cp.async.wait_group %0;\n" :: "n"(N) : "memory");
}
__device__ __forceinline__ void cp_wait_n(int n) {
    switch (n) {                         // resolved at compile time in unrolled code
        case 0: cp_wait<0>(); break;
        case 1: cp_wait<1>(); break;
        default: cp_wait<DEPTH - 1>(); break;
    }
}

// 6 n-gram hash indices for position s (7-step shared rolling chain).
__device__ __forceinline__ void compute_idx(const int* __restrict__ trow,
                                            int s, int idx[6]) {
    const int x0 = __ldg(&trow[s]);
    int h = x0;
#pragma unroll
    for (int j = 1; j <= 7; j++) {
        const int prev = (s - j >= 0) ? __ldg(&trow[s - j]) : 0;
        h = (h * HBASE + prev) % HVOC;
        if (j >= 2) idx[j - 2] = (s >= j) ? h : x0;   // n = j+1
    }
}

// Issue 6 row gathers for position (sbase+p) into smem stage st via cp.async.
__device__ __forceinline__ void issue_pos(const int* __restrict__ trow,
                                          const float* __restrict__ tables,
                                          int sbase, int p, char* wbuf, int st,
                                          int lane) {
    int idx[6];
    compute_idx(trow, sbase + p, idx);
    const uint32_t stage = smem_u32(wbuf) + st * STAGE_BYTES + lane * 16;
#pragma unroll
    for (int k = 0; k < 6; k++) {
        const float* src = tables + ((long)k * HVOC + (long)idx[k]) * EDIM + lane * 4;
        cp16(stage + k * ROWB, src);
    }
    cp_commit();
}

__global__ __launch_bounds__(WPB * 32) void ngram_embed_kernel(
    const int* __restrict__ tokens,     // (B, S) int32
    const float* __restrict__ tables,   // (6, V, D) fp32
    float* __restrict__ out)            // (B, S, D) fp32
{
    extern __shared__ char smem[];

    const int warp_in_blk = threadIdx.x >> 5;
    const int lane  = threadIdx.x & 31;
    const int gwarp = blockIdx.x * WPB + warp_in_blk;
    if (gwarp >= NWARPS) return;

    char* wbuf = smem + warp_in_blk * WARP_SMEM;

    const int pos0  = gwarp * PPW;           // SEQ % PPW == 0 -> same token row
    const int b     = pos0 >> 11;
    const int sbase = pos0 & (SEQ - 1);

    const int* __restrict__ trow = tokens + (long)b * SEQ;
    float4* __restrict__ orow = reinterpret_cast<float4*>(out + (long)pos0 * EDIM);

    // Prologue: fill DEPTH stages.
#pragma unroll
    for (int p = 0; p < DEPTH; p++)
        issue_pos(trow, tables, sbase, p, wbuf, p, lane);

    const float inv6 = 1.0f / 6.0f;

#pragma unroll
    for (int j = 0; j < PPW; j++) {
        // Groups pending before this wait: min(j+DEPTH, PPW) - j.
        // Need group j done -> wait until pending <= that - 1.
        const int pend = ((j + DEPTH < PPW) ? (j + DEPTH) : PPW) - j - 1;
        cp_wait_n(pend);

        const int st = j % DEPTH;
        const float4* rows = reinterpret_cast<const float4*>(
            wbuf + st * STAGE_BYTES) + lane;   // lane reads its own 16B per row

        float4 acc = make_float4(0.f, 0.f, 0.f, 0.f);
#pragma unroll
        for (int k = 0; k < 6; k++) {
            const float4 v = rows[k * (ROWB / 16)];
            acc.x += v.x; acc.y += v.y; acc.z += v.z; acc.w += v.w;
        }
        acc.x *= inv6; acc.y *= inv6; acc.z *= inv6; acc.w *= inv6;
        __stcs(&orow[(long)j * (EDIM / 4) + lane], acc);

        // Refill freed stage with position j+DEPTH (same stage slot: (j+DEPTH)%DEPTH == st).
        if (j + DEPTH < PPW)
            issue_pos(trow, tables, sbase, j + DEPTH, wbuf, st, lane);
    }
}

extern "C" void kernel_launch(void* const* d_in, const int* in_sizes, int n_in,
                              void* d_out, int out_size) {
    const int*   tokens = (const int*)d_in[0];
    const float* tables = (const float*)d_in[1];
    float*       out    = (float*)d_out;

    cudaFuncSetAttribute(ngram_embed_kernel,
                         cudaFuncAttributeMaxDynamicSharedMemorySize, BLOCK_SMEM);

    ngram_embed_kernel<<<NBLOCKS, WPB * 32, BLOCK_SMEM>>>(tokens, tables, out);
}

// round 6
// speedup vs baseline: 1.0610x; 1.0610x over previous
#include <cuda_runtime.h>
#include <cuda_bf16.h>

#define BATCH 32
#define SEQ   2048
#define EDIM  128
#define HVOC  500000
#define HBASE 257
#define NPOS  (BATCH * SEQ)

// One warp per (b, s) position — the empirically best shape (max occupancy,
// 30 regs). Gathers bypass L1 (__ldcg, use-once rows); output uses streaming
// stores (__stcs) to avoid polluting L2's gather working set.
__global__ __launch_bounds__(256) void ngram_embed_kernel(
    const int* __restrict__ tokens,     // (B, S) int32
    const float* __restrict__ tables,   // (6, V, D) fp32
    float* __restrict__ out)            // (B, S, D) fp32
{
    const int gwarp = (blockIdx.x * blockDim.x + threadIdx.x) >> 5;
    const int lane  = threadIdx.x & 31;
    if (gwarp >= NPOS) return;

    const int b = gwarp >> 11;       // / SEQ
    const int s = gwarp & (SEQ - 1); // % SEQ

    const int* __restrict__ trow = tokens + (long)b * SEQ;
    const int x0 = __ldg(&trow[s]);

    // Incremental rolling hash: after j steps the value equals the reference
    // hash for n = j+1. Record n in {3..8} (j in {2..7}); for s < n-1 the raw
    // byte is used instead.
    int idx[6];
    int h = x0;
#pragma unroll
    for (int j = 1; j <= 7; j++) {
        const int prev = (s - j >= 0) ? __ldg(&trow[s - j]) : 0;
        h = (h * HBASE + prev) % HVOC;   // < 257*500000 + 255 < 2^31
        if (j >= 2) idx[j - 2] = (s >= j) ? h : x0;
    }

    // 6 independent 512B gathers, one float4 per lane, L1-bypassed.
    float4 v[6];
#pragma unroll
    for (int k = 0; k < 6; k++) {
        const float4* __restrict__ row = reinterpret_cast<const float4*>(
            tables + ((long)k * HVOC + (long)idx[k]) * EDIM);
        v[k] = __ldcg(&row[lane]);
    }

    const float inv6 = 1.0f / 6.0f;
    float4 acc;
    acc.x = ((v[0].x + v[1].x) + (v[2].x + v[3].x)) + (v[4].x + v[5].x);
    acc.y = ((v[0].y + v[1].y) + (v[2].y + v[3].y)) + (v[4].y + v[5].y);
    acc.z = ((v[0].z + v[1].z) + (v[2].z + v[3].z)) + (v[4].z + v[5].z);
    acc.w = ((v[0].w + v[1].w) + (v[2].w + v[3].w)) + (v[4].w + v[5].w);
    acc.x *= inv6; acc.y *= inv6; acc.z *= inv6; acc.w *= inv6;

    __stcs(reinterpret_cast<float4*>(out + (long)gwarp * EDIM) + lane, acc);
}

extern "C" void kernel_launch(void* const* d_in, const int* in_sizes, int n_in,
                              void* d_out, int out_size) {
    const int*   tokens = (const int*)d_in[0];
    const float* tables = (const float*)d_in[1];
    float*       out    = (float*)d_out;

    const int threads = 256;                  // 8 warps = 8 consecutive positions
    const int warps_per_block = threads / 32;
    const int blocks = (NPOS + warps_per_block - 1) / warps_per_block;
    ngram_embed_kernel<<<blocks, threads>>>(tokens, tables, out);
}